// round 5
// baseline (speedup 1.0000x reference)
#include <cuda_runtime.h>

#define BATCH 8
#define CIN   64
#define HH    128
#define WW    128
#define HWSZ  (HH * WW)
#define NGRP  8
#define CG    8
#define OG    8
#define OFFC  18

#define TROWS 12           // smem tile rows per deform block (h0-5 .. h0+6)
#define TSTR  (TROWS * WW) // float2 stride per channel in tile

__device__ float  g_off[BATCH * OFFC * HWSZ];       // offsets [b][18][h][w]
__device__ float4 g_w4[BATCH * 9 * HWSZ];           // remapped bilinear weights
__device__ unsigned g_meta[BATCH * 9 * HWSZ];       // y0c | y1c<<8 | xp<<16

// ---- packed f32x2 helpers (Blackwell) -------------------------------------
__device__ __forceinline__ unsigned long long pk2(float lo, float hi) {
    unsigned long long r;
    asm("mov.b64 %0, {%1,%2};" : "=l"(r) : "f"(lo), "f"(hi));
    return r;
}
__device__ __forceinline__ void upk2(unsigned long long v, float& lo, float& hi) {
    asm("mov.b64 {%0,%1}, %2;" : "=f"(lo), "=f"(hi) : "l"(v));
}
__device__ __forceinline__ unsigned long long ffma2(
    unsigned long long a, unsigned long long b, unsigned long long c) {
    unsigned long long d;
    asm("fma.rn.f32x2 %0, %1, %2, %3;" : "=l"(d) : "l"(a), "l"(b), "l"(c));
    return d;
}

// ---------------------------------------------------------------------------
// Kernel 1: offset conv (64ch -> 18ch, 3x3, pad 1) + PReLU  (unchanged)
// ---------------------------------------------------------------------------
__global__ __launch_bounds__(128) void offset_conv_kernel(
    const float* __restrict__ x, const float* __restrict__ ow,
    const float* __restrict__ ob, const float* __restrict__ pa)
{
    __shared__ __align__(16) float ws[CIN * 9 * 20];

    int tx = threadIdx.x, ty = threadIdx.y;
    int tid = ty * 32 + tx;
    for (int i = tid; i < CIN * 9 * 18; i += 128) {
        int c = i / 162;
        int r = i - c * 162;
        int tap = r / 18;
        int j = r - tap * 18;
        ws[(c * 9 + tap) * 20 + j] = ow[j * (CIN * 9) + c * 9 + tap];
    }
    __syncthreads();

    int b  = blockIdx.z;
    int w0 = blockIdx.x * 32 + tx;
    int h0 = blockIdx.y * 8 + ty * 2;

    bool vr[4], vc[3];
#pragma unroll
    for (int r = 0; r < 4; r++) vr[r] = (unsigned)(h0 - 1 + r) < (unsigned)HH;
#pragma unroll
    for (int cc = 0; cc < 3; cc++) vc[cc] = (unsigned)(w0 - 1 + cc) < (unsigned)WW;

    unsigned long long acc2[2][9];
#pragma unroll
    for (int jj = 0; jj < 9; jj++) {
        unsigned long long t = pk2(ob[2 * jj], ob[2 * jj + 1]);
        acc2[0][jj] = t;
        acc2[1][jj] = t;
    }

    const float* xbase = x + ((size_t)(b * CIN) * HH + (h0 - 1)) * WW + (w0 - 1);

    for (int c = 0; c < CIN; c++) {
        const float* px = xbase + c * HWSZ;
        float xv[4][3];
#pragma unroll
        for (int r = 0; r < 4; r++)
#pragma unroll
            for (int cc = 0; cc < 3; cc++)
                xv[r][cc] = (vr[r] && vc[cc]) ? __ldg(px + r * WW + cc) : 0.f;

        const float* wrow = &ws[c * 180];
#pragma unroll
        for (int tap = 0; tap < 9; tap++) {
            const char* wp = (const char*)(wrow + tap * 20);
            ulonglong2 q0 = *(const ulonglong2*)(wp);
            ulonglong2 q1 = *(const ulonglong2*)(wp + 16);
            ulonglong2 q2 = *(const ulonglong2*)(wp + 32);
            ulonglong2 q3 = *(const ulonglong2*)(wp + 48);
            unsigned long long q8 = *(const unsigned long long*)(wp + 64);
            unsigned long long wj[9] = {q0.x, q0.y, q1.x, q1.y,
                                        q2.x, q2.y, q3.x, q3.y, q8};
            int ky = tap / 3;
            int kx = tap - ky * 3;
            unsigned long long a0 = pk2(xv[ky][kx],     xv[ky][kx]);
            unsigned long long a1 = pk2(xv[ky + 1][kx], xv[ky + 1][kx]);
#pragma unroll
            for (int jj = 0; jj < 9; jj++) {
                acc2[0][jj] = ffma2(a0, wj[jj], acc2[0][jj]);
                acc2[1][jj] = ffma2(a1, wj[jj], acc2[1][jj]);
            }
        }
    }

    float a = pa[0];
#pragma unroll
    for (int i = 0; i < 2; i++)
#pragma unroll
        for (int jj = 0; jj < 9; jj++) {
            float v0, v1;
            upk2(acc2[i][jj], v0, v1);
            v0 = v0 > 0.f ? v0 : a * v0;
            v1 = v1 > 0.f ? v1 : a * v1;
            int hrow = h0 + i;
            g_off[((b * OFFC + 2 * jj)     * HH + hrow) * WW + w0] = v0;
            g_off[((b * OFFC + 2 * jj + 1) * HH + hrow) * WW + w0] = v1;
        }
}

// ---------------------------------------------------------------------------
// Kernel 2: bilinear precompute with pair-remapped x weights.
// For each (b,k,h,w): contribution = wy0*(A*v[y0c][xp]+B*v[y0c][xp+1])
//                                  + wy1*(A*v[y1c][xp]+B*v[y1c][xp+1])
// stored distributed: w4 = (wy0*A, wy0*B, wy1*A, wy1*B); meta = y0c|y1c<<8|xp<<16.
// ---------------------------------------------------------------------------
__global__ __launch_bounds__(256) void bilin_kernel()
{
    int idx = blockIdx.x * 256 + threadIdx.x;
    const int total = BATCH * 9 * HWSZ;
    if (idx >= total) return;
    int w = idx & 127;
    int t = idx >> 7;
    int h = t & 127;
    int bk = t >> 7;
    int k = bk % 9;
    int b = bk / 9;

    float dy = g_off[((b * OFFC + 2 * k)     * HH + h) * WW + w];
    float dx = g_off[((b * OFFC + 2 * k + 1) * HH + h) * WW + w];
    int ky = k / 3 - 1;
    int kx = k - (k / 3) * 3 - 1;
    float py = (float)(h + ky) + dy;
    float px = (float)(w + kx) + dx;
    float y0f = floorf(py), x0f = floorf(px);
    float ly = py - y0f, lx = px - x0f;
    int y0 = (int)y0f, x0 = (int)x0f;
    float hy = 1.f - ly, hx = 1.f - lx;

    float wy0 = ((unsigned)y0       < (unsigned)HH) ? hy : 0.f;
    float wy1 = ((unsigned)(y0 + 1) < (unsigned)HH) ? ly : 0.f;
    float wx0 = ((unsigned)x0       < (unsigned)WW) ? hx : 0.f;
    float wx1 = ((unsigned)(x0 + 1) < (unsigned)WW) ? lx : 0.f;

    int xp; float A, B;
    if (x0 < 0)        { xp = 0;   A = wx1; B = 0.f; }
    else if (x0 > 126) { xp = 126; A = 0.f; B = wx0; }
    else               { xp = x0;  A = wx0; B = wx1; }

    int y0c = min(max(y0, 0), HH - 1);
    int y1c = min(max(y0 + 1, 0), HH - 1);

    g_w4[idx]   = make_float4(wy0 * A, wy0 * B, wy1 * A, wy1 * B);
    g_meta[idx] = (unsigned)y0c | ((unsigned)y1c << 8) | ((unsigned)xp << 16);
}

// ---------------------------------------------------------------------------
// Kernel 3: grouped deformable conv with smem duplicated-pair x tile.
// grid (64 h-pairs, 8 b, 8 g); block 256 = 2 rows x 128 px, 1 px/thread.
// Dynamic smem: tile2[8c][12r][128] float2 (dup pairs) + s_w[9][8][8].
// ---------------------------------------------------------------------------
__global__ __launch_bounds__(256) void deform_kernel(
    const float* __restrict__ x, const float* __restrict__ dw,
    const float* __restrict__ db, float* __restrict__ out)
{
    extern __shared__ __align__(16) char dsm[];
    float2* tile2 = (float2*)dsm;                       // 8*12*128 f2 = 96KB
    float*  s_w   = (float*)(dsm + CG * TSTR * 8);      // 2304B

    int tid = threadIdx.x;
    int h0 = blockIdx.x * 2;
    int b  = blockIdx.y;
    int g  = blockIdx.z;
    int hbase = h0 - 5;

    // stage weights: s_w[k][c][oo]
    for (int i = tid; i < 9 * CG * OG; i += 256) {
        int k  = i >> 6;
        int rc = i & 63;
        int c  = rc >> 3;
        int oo = rc & 7;
        s_w[i] = dw[((g * 8 + oo) * 8 + c) * 9 + k];
    }

    // stage x tile as duplicated pairs: tile2[c][r][x] = (v[x], v[min(x+1,127)])
    const float* xg = x + (size_t)(b * CIN + g * CG) * HWSZ;
    for (int id = tid; id < CG * TROWS * 32; id += 256) {
        int c  = id / (TROWS * 32);
        int rr = id - c * (TROWS * 32);
        int r  = rr >> 5;
        int xq = rr & 31;
        int xx = xq * 4;
        int ar = min(max(hbase + r, 0), HH - 1);
        const float* row = xg + c * HWSZ + ar * WW;
        float4 v4 = *(const float4*)(row + xx);
        float vnext = (xx + 4 <= 127) ? row[xx + 4] : v4.w;
        float2* dst = tile2 + c * TSTR + r * WW + xx;
        dst[0] = make_float2(v4.x, v4.y);
        dst[1] = make_float2(v4.y, v4.z);
        dst[2] = make_float2(v4.z, v4.w);
        dst[3] = make_float2(v4.w, vnext);
    }
    __syncthreads();

    int pxl = tid & 127;
    int hh  = h0 + (tid >> 7);

    unsigned long long acc2[4];
#pragma unroll
    for (int q = 0; q < 4; q++)
        acc2[q] = pk2(db[g * 8 + 2 * q], db[g * 8 + 2 * q + 1]);

#pragma unroll 1
    for (int k = 0; k < 9; k++) {
        int midx = ((b * 9 + k) * HH + hh) * WW + pxl;
        float4 w4 = __ldg(&g_w4[midx]);
        unsigned meta = __ldg(&g_meta[midx]);
        int y0c =  meta        & 255;
        int y1c = (meta >> 8)  & 255;
        int xp  =  meta >> 16;
        int r0 = y0c - hbase;
        int r1 = y1c - hbase;
        bool in0 = (unsigned)r0 < (unsigned)TROWS;
        bool in1 = (unsigned)r1 < (unsigned)TROWS;
        int t0 = r0 * WW + xp;
        int t1 = r1 * WW + xp;
        const float* f0 = xg + y0c * WW + xp;   // fallback bases (rare)
        const float* f1 = xg + y1c * WW + xp;

        const float* wk = &s_w[k * 64];
#pragma unroll
        for (int c = 0; c < 8; c++) {
            float2 P0, P1;
            if (in0) P0 = tile2[c * TSTR + t0];
            else     P0 = make_float2(__ldg(f0 + c * HWSZ), __ldg(f0 + c * HWSZ + 1));
            if (in1) P1 = tile2[c * TSTR + t1];
            else     P1 = make_float2(__ldg(f1 + c * HWSZ), __ldg(f1 + c * HWSZ + 1));
            float v = w4.x * P0.x + w4.y * P0.y + w4.z * P1.x + w4.w * P1.y;
            ulonglong2 u0 = *(const ulonglong2*)(wk + c * 8);
            ulonglong2 u1 = *(const ulonglong2*)(wk + c * 8 + 4);
            unsigned long long v2 = pk2(v, v);
            acc2[0] = ffma2(v2, u0.x, acc2[0]);
            acc2[1] = ffma2(v2, u0.y, acc2[1]);
            acc2[2] = ffma2(v2, u1.x, acc2[2]);
            acc2[3] = ffma2(v2, u1.y, acc2[3]);
        }
    }

#pragma unroll
    for (int q = 0; q < 4; q++) {
        float v0, v1;
        upk2(acc2[q], v0, v1);
        out[((b * CIN + g * 8 + 2 * q)     * HH + hh) * WW + pxl] = v0;
        out[((b * CIN + g * 8 + 2 * q + 1) * HH + hh) * WW + pxl] = v1;
    }
}

// ---------------------------------------------------------------------------
extern "C" void kernel_launch(void* const* d_in, const int* in_sizes, int n_in,
                              void* d_out, int out_size)
{
    const float* x  = (const float*)d_in[0];
    const float* ow = (const float*)d_in[1];
    const float* ob = (const float*)d_in[2];
    const float* pa = (const float*)d_in[3];
    const float* dw = (const float*)d_in[4];
    const float* db = (const float*)d_in[5];
    float* out = (float*)d_out;

    const int dyn = CG * TSTR * 8 + 9 * CG * OG * 4;   // 96KB tile + 2.25KB weights
    static int smem_set = 0;
    // idempotent attribute set (host-side, not a stream op; safe under capture)
    cudaFuncSetAttribute(deform_kernel,
                         cudaFuncAttributeMaxDynamicSharedMemorySize, dyn);
    (void)smem_set;

    offset_conv_kernel<<<dim3(4, 16, 8), dim3(32, 4)>>>(x, ow, ob, pa);
    const int totB = BATCH * 9 * HWSZ;
    bilin_kernel<<<(totB + 255) / 256, 256>>>();
    deform_kernel<<<dim3(HH / 2, BATCH, NGRP), 256, dyn>>>(x, dw, db, out);
}